// round 1
// baseline (speedup 1.0000x reference)
#include <cuda_runtime.h>
#include <math.h>

// Problem constants
#define BB    2
#define TT    1024
#define DD    1024
#define HH    16
#define DHH   64
#define NLAY  4
#define NLEV  8
#define DFF   4096
#define NROWS (BB*TT)          // 2048 token rows

// Scratch (device globals — no allocation allowed)
__device__ float g_h[NROWS * DD];             // adaln output
__device__ float g_qkv[NROWS * 3 * DD];       // qkv projections
__device__ float g_attn[NROWS * DD];          // attention output (pre out-proj)
__device__ float g_f1[NROWS * DFF];           // ffn hidden
__device__ float g_scores[(size_t)BB * HH * TT * TT];  // attention scores/probs (128 MiB)

__device__ __forceinline__ float gelu_exact(float x) {
    return 0.5f * x * (1.0f + erff(x * 0.70710678118654752f));
}

// ---------------------------------------------------------------------------
// AdaLN: per-row layernorm + C*(1-K*h)*h + exp(loggamma)*h + beta, times mask
// ---------------------------------------------------------------------------
__global__ void adaln_kernel(const float* __restrict__ x, const float* __restrict__ m,
                             const int* __restrict__ l, const float* __restrict__ emb,
                             float* __restrict__ out) {
    int row = blockIdx.x;
    int b = row / TT;
    float mv = m[row];
    const float* xr = x + (size_t)row * DD;
    float* orow = out + (size_t)row * DD;
    int tid = threadIdx.x;

    float v[4];
    float s = 0.f, ss = 0.f;
#pragma unroll
    for (int u = 0; u < 4; u++) {
        v[u] = xr[tid + u * 256];
        s += v[u];
        ss += v[u] * v[u];
    }
    __shared__ float sh1[256];
    __shared__ float sh2[256];
    sh1[tid] = s; sh2[tid] = ss;
    __syncthreads();
    for (int stp = 128; stp > 0; stp >>= 1) {
        if (tid < stp) { sh1[tid] += sh1[tid + stp]; sh2[tid] += sh2[tid + stp]; }
        __syncthreads();
    }
    float mu  = sh1[0] * (1.0f / DD);
    float var = sh2[0] * (1.0f / DD) - mu * mu;
    float rinv = rsqrtf(var + 1e-5f);

    const float* g = emb + (size_t)l[b] * (2 * DD);
#pragma unroll
    for (int u = 0; u < 4; u++) {
        int d = tid + u * 256;
        float hn = (v[u] - mu) * rinv;
        float h = 2.0f * (1.0f - 0.1f * hn) * hn;
        orow[d] = (expf(g[d]) * h + g[DD + d]) * mv;
    }
}

// ---------------------------------------------------------------------------
// Generic tiled SGEMM: C = epi(A @ W + bias)
// EPI: 0 = none, 1 = GELU, 2 = residual+mask  C = (res + gemm + bias)*m[row]
// ---------------------------------------------------------------------------
template <int EPI>
__global__ void gemm_kernel(const float* __restrict__ A, const float* __restrict__ W,
                            const float* __restrict__ bias, const float* __restrict__ res,
                            const float* __restrict__ m, float* __restrict__ C,
                            int M, int N, int K) {
    __shared__ float As[16][68];
    __shared__ float Bs[16][64];
    int tid = threadIdx.x;
    int tx = tid & 15, ty = tid >> 4;
    int row0 = blockIdx.y * 64, col0 = blockIdx.x * 64;

    float acc[4][4] = {};

    for (int k0 = 0; k0 < K; k0 += 16) {
#pragma unroll
        for (int i = tid; i < 1024; i += 256) {
            int r = i >> 4, c = i & 15;
            As[c][r] = A[(size_t)(row0 + r) * K + k0 + c];
        }
#pragma unroll
        for (int i = tid; i < 1024; i += 256) {
            int r = i >> 6, c = i & 63;
            Bs[r][c] = W[(size_t)(k0 + r) * N + col0 + c];
        }
        __syncthreads();
#pragma unroll
        for (int k = 0; k < 16; k++) {
            float ra[4], rb[4];
#pragma unroll
            for (int a = 0; a < 4; a++) ra[a] = As[k][ty * 4 + a];
#pragma unroll
            for (int b2 = 0; b2 < 4; b2++) rb[b2] = Bs[k][tx * 4 + b2];
#pragma unroll
            for (int a = 0; a < 4; a++)
#pragma unroll
                for (int b2 = 0; b2 < 4; b2++)
                    acc[a][b2] += ra[a] * rb[b2];
        }
        __syncthreads();
    }

#pragma unroll
    for (int a = 0; a < 4; a++) {
        int gm = row0 + ty * 4 + a;
        float mr = (EPI == 2) ? m[gm] : 0.f;
#pragma unroll
        for (int b2 = 0; b2 < 4; b2++) {
            int gn = col0 + tx * 4 + b2;
            float v = acc[a][b2];
            if (bias) v += bias[gn];
            if (EPI == 1) v = gelu_exact(v);
            if (EPI == 2) v = (res[(size_t)gm * N + gn] + v) * mr;
            C[(size_t)gm * N + gn] = v;
        }
    }
}

// ---------------------------------------------------------------------------
// Attention scores: E[bh,i,j] = 0.125 * q·k ; causal-dead tiles skipped
// ---------------------------------------------------------------------------
__global__ void scores_kernel(const float* __restrict__ qkv, float* __restrict__ E) {
    int z = blockIdx.z; int b = z >> 4; int h = z & 15;
    int it = blockIdx.y, jt = blockIdx.x;
    if (jt > it) return;
    __shared__ float Qs[64][68];
    __shared__ float Ks[64][68];
    int tid = threadIdx.x;
    int tx = tid & 15, ty = tid >> 4;
    int i0 = it * 64, j0 = jt * 64;
    const float* qb = qkv + (size_t)b * TT * 3 * DD + h * DHH;
    const float* kb = qb + DD;
#pragma unroll
    for (int i = tid; i < 4096; i += 256) {
        int r = i >> 6, c = i & 63;
        Qs[c][r] = qb[(size_t)(i0 + r) * (3 * DD) + c];
        Ks[c][r] = kb[(size_t)(j0 + r) * (3 * DD) + c];
    }
    __syncthreads();
    float acc[4][4] = {};
#pragma unroll 4
    for (int d = 0; d < 64; d++) {
        float rq[4], rk[4];
#pragma unroll
        for (int a = 0; a < 4; a++) rq[a] = Qs[d][ty * 4 + a];
#pragma unroll
        for (int b2 = 0; b2 < 4; b2++) rk[b2] = Ks[d][tx * 4 + b2];
#pragma unroll
        for (int a = 0; a < 4; a++)
#pragma unroll
            for (int b2 = 0; b2 < 4; b2++)
                acc[a][b2] += rq[a] * rk[b2];
    }
    float* Eb = E + (size_t)z * TT * TT;
#pragma unroll
    for (int a = 0; a < 4; a++)
#pragma unroll
        for (int b2 = 0; b2 < 4; b2++)
            Eb[(size_t)(i0 + ty * 4 + a) * TT + j0 + tx * 4 + b2] = acc[a][b2] * 0.125f;
}

// ---------------------------------------------------------------------------
// Masked causal softmax over j; zeros for masked j so AV is a plain GEMM.
// ---------------------------------------------------------------------------
__global__ void softmax_kernel(const float* __restrict__ m, float* __restrict__ E) {
    int bh = blockIdx.y; int b = bh >> 4;
    int i = blockIdx.x;
    float* row = E + ((size_t)bh * TT + i) * TT;
    int tid = threadIdx.x;
    __shared__ float sh[256];

    float mi = m[b * TT + i];
    if (mi == 0.f) {
#pragma unroll
        for (int u = 0; u < 4; u++) row[tid + u * 256] = 0.f;
        return;
    }
    float e[4]; bool val[4];
    float mx = -3.4e38f;
#pragma unroll
    for (int u = 0; u < 4; u++) {
        int j = tid + u * 256;
        bool ok = (j <= i) && (m[b * TT + j] != 0.f);
        val[u] = ok;
        e[u] = ok ? row[j] : -3.4e38f;
        mx = fmaxf(mx, e[u]);
    }
    sh[tid] = mx; __syncthreads();
    for (int s = 128; s > 0; s >>= 1) {
        if (tid < s) sh[tid] = fmaxf(sh[tid], sh[tid + s]);
        __syncthreads();
    }
    mx = sh[0]; __syncthreads();

    float p[4]; float sum = 0.f;
#pragma unroll
    for (int u = 0; u < 4; u++) {
        p[u] = val[u] ? expf(e[u] - mx) : 0.f;
        sum += p[u];
    }
    sh[tid] = sum; __syncthreads();
    for (int s = 128; s > 0; s >>= 1) {
        if (tid < s) sh[tid] += sh[tid + s];
        __syncthreads();
    }
    float inv = 1.0f / sh[0];
#pragma unroll
    for (int u = 0; u < 4; u++) row[tid + u * 256] = p[u] * inv;
}

// ---------------------------------------------------------------------------
// AV: O[b,i,h*64+d] = sum_j P[bh,i,j] * v[b,j,h,d]
// ---------------------------------------------------------------------------
__global__ void av_kernel(const float* __restrict__ E, const float* __restrict__ qkv,
                          float* __restrict__ O) {
    int z = blockIdx.z; int b = z >> 4; int h = z & 15;
    int it = blockIdx.y; int i0 = it * 64;
    __shared__ float As[16][68];
    __shared__ float Vs[16][64];
    int tid = threadIdx.x;
    int tx = tid & 15, ty = tid >> 4;
    const float* Eb = E + (size_t)z * TT * TT;
    const float* vb = qkv + (size_t)b * TT * 3 * DD + 2 * DD + h * DHH;
    float acc[4][4] = {};
    int kmax = i0 + 64;
    for (int k0 = 0; k0 < kmax; k0 += 16) {
#pragma unroll
        for (int i2 = tid; i2 < 1024; i2 += 256) {
            int r = i2 >> 4, c = i2 & 15;
            As[c][r] = Eb[(size_t)(i0 + r) * TT + k0 + c];
        }
#pragma unroll
        for (int i2 = tid; i2 < 1024; i2 += 256) {
            int r = i2 >> 6, c = i2 & 63;
            Vs[r][c] = vb[(size_t)(k0 + r) * (3 * DD) + c];
        }
        __syncthreads();
#pragma unroll
        for (int k = 0; k < 16; k++) {
            float ra[4], rb[4];
#pragma unroll
            for (int a = 0; a < 4; a++) ra[a] = As[k][ty * 4 + a];
#pragma unroll
            for (int b2 = 0; b2 < 4; b2++) rb[b2] = Vs[k][tx * 4 + b2];
#pragma unroll
            for (int a = 0; a < 4; a++)
#pragma unroll
                for (int b2 = 0; b2 < 4; b2++)
                    acc[a][b2] += ra[a] * rb[b2];
        }
        __syncthreads();
    }
    float* ob = O + (size_t)b * TT * DD + h * DHH;
#pragma unroll
    for (int a = 0; a < 4; a++)
#pragma unroll
        for (int b2 = 0; b2 < 4; b2++)
            ob[(size_t)(i0 + ty * 4 + a) * DD + tx * 4 + b2] = acc[a][b2];
}

// ---------------------------------------------------------------------------
extern "C" void kernel_launch(void* const* d_in, const int* in_sizes, int n_in,
                              void* d_out, int out_size) {
    const float* x_in    = (const float*)d_in[0];
    const float* m       = (const float*)d_in[1];
    const int*   l       = (const int*)d_in[2];
    const float* Wqkv    = (const float*)d_in[3];
    const float* Wout    = (const float*)d_in[4];
    const float* bout    = (const float*)d_in[5];
    const float* ad_attn = (const float*)d_in[6];
    const float* ad_ffn  = (const float*)d_in[7];
    const float* W1      = (const float*)d_in[8];
    const float* b1      = (const float*)d_in[9];
    const float* W2      = (const float*)d_in[10];
    const float* b2      = (const float*)d_in[11];
    float* x = (float*)d_out;   // residual stream lives in d_out

    float *h, *qkv, *attn, *f1, *scores;
    cudaGetSymbolAddress((void**)&h,      g_h);
    cudaGetSymbolAddress((void**)&qkv,    g_qkv);
    cudaGetSymbolAddress((void**)&attn,   g_attn);
    cudaGetSymbolAddress((void**)&f1,     g_f1);
    cudaGetSymbolAddress((void**)&scores, g_scores);

    cudaMemcpyAsync(x, x_in, sizeof(float) * (size_t)NROWS * DD,
                    cudaMemcpyDeviceToDevice);

    for (int i = 0; i < NLAY; i++) {
        // attention sub-block
        adaln_kernel<<<NROWS, 256>>>(x, m, l, ad_attn + (size_t)i * NLEV * 2 * DD, h);
        gemm_kernel<0><<<dim3(3 * DD / 64, NROWS / 64), 256>>>(
            h, Wqkv + (size_t)i * DD * 3 * DD, nullptr, nullptr, nullptr,
            qkv, NROWS, 3 * DD, DD);
        scores_kernel<<<dim3(TT / 64, TT / 64, BB * HH), 256>>>(qkv, scores);
        softmax_kernel<<<dim3(TT, BB * HH), 256>>>(m, scores);
        av_kernel<<<dim3(1, TT / 64, BB * HH), 256>>>(scores, qkv, attn);
        gemm_kernel<2><<<dim3(DD / 64, NROWS / 64), 256>>>(
            attn, Wout + (size_t)i * DD * DD, bout + (size_t)i * DD, x, m,
            x, NROWS, DD, DD);
        // FFN sub-block
        adaln_kernel<<<NROWS, 256>>>(x, m, l, ad_ffn + (size_t)i * NLEV * 2 * DD, h);
        gemm_kernel<1><<<dim3(DFF / 64, NROWS / 64), 256>>>(
            h, W1 + (size_t)i * DD * DFF, b1 + (size_t)i * DFF, nullptr, nullptr,
            f1, NROWS, DFF, DD);
        gemm_kernel<2><<<dim3(DD / 64, NROWS / 64), 256>>>(
            f1, W2 + (size_t)i * DFF * DD, b2 + (size_t)i * DD, x, m,
            x, NROWS, DD, DFF);
    }
}

// round 2
// speedup vs baseline: 1.7120x; 1.7120x over previous
#include <cuda_runtime.h>
#include <math.h>
#include <stdint.h>

// Problem constants
#define BB    2
#define TT    1024
#define DD    1024
#define HH    16
#define DHH   64
#define NLAY  4
#define NLEV  8
#define DFF   4096
#define NROWS (BB*TT)          // 2048 token rows

// Scratch (device globals — no allocation allowed)
__device__ float g_h[NROWS * DD];             // adaln output
__device__ float g_qkv[NROWS * 3 * DD];       // qkv projections
__device__ float g_attn[NROWS * DD];          // attention output (pre out-proj)
__device__ float g_f1[NROWS * DFF];           // ffn hidden
__device__ float g_scores[(size_t)BB * HH * TT * TT];  // attention scores/probs

__device__ __forceinline__ float gelu_exact(float x) {
    return 0.5f * x * (1.0f + erff(x * 0.70710678118654752f));
}

__device__ __forceinline__ float cvt_tf32(float x) {
    uint32_t u;
    asm("cvt.rna.tf32.f32 %0, %1;" : "=r"(u) : "f"(x));
    return __uint_as_float(u);
}

// ---------------------------------------------------------------------------
// AdaLN
// ---------------------------------------------------------------------------
__global__ void adaln_kernel(const float* __restrict__ x, const float* __restrict__ m,
                             const int* __restrict__ l, const float* __restrict__ emb,
                             float* __restrict__ out) {
    int row = blockIdx.x;
    int b = row / TT;
    float mv = m[row];
    const float* xr = x + (size_t)row * DD;
    float* orow = out + (size_t)row * DD;
    int tid = threadIdx.x;

    float v[4];
    float s = 0.f, ss = 0.f;
#pragma unroll
    for (int u = 0; u < 4; u++) {
        v[u] = xr[tid + u * 256];
        s += v[u];
        ss += v[u] * v[u];
    }
    __shared__ float sh1[256];
    __shared__ float sh2[256];
    sh1[tid] = s; sh2[tid] = ss;
    __syncthreads();
    for (int stp = 128; stp > 0; stp >>= 1) {
        if (tid < stp) { sh1[tid] += sh1[tid + stp]; sh2[tid] += sh2[tid + stp]; }
        __syncthreads();
    }
    float mu  = sh1[0] * (1.0f / DD);
    float var = sh2[0] * (1.0f / DD) - mu * mu;
    float rinv = rsqrtf(var + 1e-5f);

    const float* g = emb + (size_t)l[b] * (2 * DD);
#pragma unroll
    for (int u = 0; u < 4; u++) {
        int d = tid + u * 256;
        float hn = (v[u] - mu) * rinv;
        float h = 2.0f * (1.0f - 0.1f * hn) * hn;
        orow[d] = (expf(g[d]) * h + g[DD + d]) * mv;
    }
}

// ---------------------------------------------------------------------------
// tf32 tensor-core GEMM: C = epi(A @ W + bias)
// Block tile 128x128, BK=32, 256 threads (8 warps, 2x4), warp tile 64x32,
// mma.sync.m16n8k8.tf32, fp32 accumulate.
// EPI: 0 = none, 1 = GELU, 2 = residual+mask  C = (res + gemm + bias)*m[row]
// ---------------------------------------------------------------------------
template <int EPI>
__global__ void __launch_bounds__(256)
gemm_tf32(const float* __restrict__ A, const float* __restrict__ W,
          const float* __restrict__ bias, const float* __restrict__ res,
          const float* __restrict__ m, float* __restrict__ C,
          int M, int N, int K) {
    __shared__ __align__(16) float As[128][36];   // [m][k], stride 36 -> conflict-free frags
    __shared__ __align__(16) float Bs[32][136];   // [k][n], stride 136 -> conflict-free frags

    int tid  = threadIdx.x;
    int warp = tid >> 5, lane = tid & 31;
    int g = lane >> 2, t = lane & 3;          // groupID, threadID-in-group
    int warpm = warp >> 2, warpn = warp & 3;  // 2 x 4 warp grid
    int row0 = blockIdx.y * 128, col0 = blockIdx.x * 128;

    float acc[4][4][4] = {};                  // [mi][ni][c0..c3]

    for (int k0 = 0; k0 < K; k0 += 32) {
        // global -> smem (with tf32 rounding)
#pragma unroll
        for (int i = 0; i < 4; i++) {
            int idx = tid + i * 256;          // 1024 float4 = 128x32
            int r = idx >> 3, c4 = (idx & 7) * 4;
            float4 v = *(const float4*)(A + (size_t)(row0 + r) * K + k0 + c4);
            float4 w;
            w.x = cvt_tf32(v.x); w.y = cvt_tf32(v.y);
            w.z = cvt_tf32(v.z); w.w = cvt_tf32(v.w);
            *(float4*)&As[r][c4] = w;
        }
#pragma unroll
        for (int i = 0; i < 4; i++) {
            int idx = tid + i * 256;          // 1024 float4 = 32x128
            int r = idx >> 5, c4 = (idx & 31) * 4;
            float4 v = *(const float4*)(W + (size_t)(k0 + r) * N + col0 + c4);
            float4 w;
            w.x = cvt_tf32(v.x); w.y = cvt_tf32(v.y);
            w.z = cvt_tf32(v.z); w.w = cvt_tf32(v.w);
            *(float4*)&Bs[r][c4] = w;
        }
        __syncthreads();

#pragma unroll
        for (int kk = 0; kk < 32; kk += 8) {
            uint32_t af[4][4], bf[4][2];
#pragma unroll
            for (int mi = 0; mi < 4; mi++) {
                int rb = warpm * 64 + mi * 16 + g;
                af[mi][0] = __float_as_uint(As[rb    ][kk + t    ]);
                af[mi][1] = __float_as_uint(As[rb + 8][kk + t    ]);
                af[mi][2] = __float_as_uint(As[rb    ][kk + t + 4]);
                af[mi][3] = __float_as_uint(As[rb + 8][kk + t + 4]);
            }
#pragma unroll
            for (int ni = 0; ni < 4; ni++) {
                int cb = warpn * 32 + ni * 8 + g;
                bf[ni][0] = __float_as_uint(Bs[kk + t    ][cb]);
                bf[ni][1] = __float_as_uint(Bs[kk + t + 4][cb]);
            }
#pragma unroll
            for (int mi = 0; mi < 4; mi++)
#pragma unroll
                for (int ni = 0; ni < 4; ni++) {
                    asm volatile(
                        "mma.sync.aligned.m16n8k8.row.col.f32.tf32.tf32.f32 "
                        "{%0,%1,%2,%3}, {%4,%5,%6,%7}, {%8,%9}, {%0,%1,%2,%3};"
                        : "+f"(acc[mi][ni][0]), "+f"(acc[mi][ni][1]),
                          "+f"(acc[mi][ni][2]), "+f"(acc[mi][ni][3])
                        : "r"(af[mi][0]), "r"(af[mi][1]), "r"(af[mi][2]), "r"(af[mi][3]),
                          "r"(bf[ni][0]), "r"(bf[ni][1]));
                }
        }
        __syncthreads();
    }

    // epilogue
#pragma unroll
    for (int mi = 0; mi < 4; mi++) {
        int r0 = row0 + warpm * 64 + mi * 16 + g;
        int r1 = r0 + 8;
        float m0 = (EPI == 2) ? m[r0] : 0.f;
        float m1 = (EPI == 2) ? m[r1] : 0.f;
#pragma unroll
        for (int ni = 0; ni < 4; ni++) {
            int cb = col0 + warpn * 32 + ni * 8 + 2 * t;
            float v0 = acc[mi][ni][0], v1 = acc[mi][ni][1];
            float v2 = acc[mi][ni][2], v3 = acc[mi][ni][3];
            if (bias) {
                float b0 = bias[cb], b1 = bias[cb + 1];
                v0 += b0; v1 += b1; v2 += b0; v3 += b1;
            }
            if (EPI == 1) {
                v0 = gelu_exact(v0); v1 = gelu_exact(v1);
                v2 = gelu_exact(v2); v3 = gelu_exact(v3);
            }
            if (EPI == 2) {
                const float* rr0 = res + (size_t)r0 * N + cb;
                const float* rr1 = res + (size_t)r1 * N + cb;
                v0 = (rr0[0] + v0) * m0; v1 = (rr0[1] + v1) * m0;
                v2 = (rr1[0] + v2) * m1; v3 = (rr1[1] + v3) * m1;
            }
            *(float2*)(C + (size_t)r0 * N + cb) = make_float2(v0, v1);
            *(float2*)(C + (size_t)r1 * N + cb) = make_float2(v2, v3);
        }
    }
}

// ---------------------------------------------------------------------------
// Attention scores: E[bh,i,j] = 0.125 * q·k ; causal-dead tiles skipped
// ---------------------------------------------------------------------------
__global__ void scores_kernel(const float* __restrict__ qkv, float* __restrict__ E) {
    int z = blockIdx.z; int b = z >> 4; int h = z & 15;
    int it = blockIdx.y, jt = blockIdx.x;
    if (jt > it) return;
    __shared__ float Qs[64][68];
    __shared__ float Ks[64][68];
    int tid = threadIdx.x;
    int tx = tid & 15, ty = tid >> 4;
    int i0 = it * 64, j0 = jt * 64;
    const float* qb = qkv + (size_t)b * TT * 3 * DD + h * DHH;
    const float* kb = qb + DD;
#pragma unroll
    for (int i = tid; i < 4096; i += 256) {
        int r = i >> 6, c = i & 63;
        Qs[c][r] = qb[(size_t)(i0 + r) * (3 * DD) + c];
        Ks[c][r] = kb[(size_t)(j0 + r) * (3 * DD) + c];
    }
    __syncthreads();
    float acc[4][4] = {};
#pragma unroll 4
    for (int d = 0; d < 64; d++) {
        float rq[4], rk[4];
#pragma unroll
        for (int a = 0; a < 4; a++) rq[a] = Qs[d][ty * 4 + a];
#pragma unroll
        for (int b2 = 0; b2 < 4; b2++) rk[b2] = Ks[d][tx * 4 + b2];
#pragma unroll
        for (int a = 0; a < 4; a++)
#pragma unroll
            for (int b2 = 0; b2 < 4; b2++)
                acc[a][b2] += rq[a] * rk[b2];
    }
    float* Eb = E + (size_t)z * TT * TT;
#pragma unroll
    for (int a = 0; a < 4; a++)
#pragma unroll
        for (int b2 = 0; b2 < 4; b2++)
            Eb[(size_t)(i0 + ty * 4 + a) * TT + j0 + tx * 4 + b2] = acc[a][b2] * 0.125f;
}

// ---------------------------------------------------------------------------
// Masked causal softmax over j; zeros for masked j so AV is a plain GEMM.
// ---------------------------------------------------------------------------
__global__ void softmax_kernel(const float* __restrict__ m, float* __restrict__ E) {
    int bh = blockIdx.y; int b = bh >> 4;
    int i = blockIdx.x;
    float* row = E + ((size_t)bh * TT + i) * TT;
    int tid = threadIdx.x;
    __shared__ float sh[256];

    float mi = m[b * TT + i];
    if (mi == 0.f) {
#pragma unroll
        for (int u = 0; u < 4; u++) row[tid + u * 256] = 0.f;
        return;
    }
    float e[4]; bool val[4];
    float mx = -3.4e38f;
#pragma unroll
    for (int u = 0; u < 4; u++) {
        int j = tid + u * 256;
        bool ok = (j <= i) && (m[b * TT + j] != 0.f);
        val[u] = ok;
        e[u] = ok ? row[j] : -3.4e38f;
        mx = fmaxf(mx, e[u]);
    }
    sh[tid] = mx; __syncthreads();
    for (int s = 128; s > 0; s >>= 1) {
        if (tid < s) sh[tid] = fmaxf(sh[tid], sh[tid + s]);
        __syncthreads();
    }
    mx = sh[0]; __syncthreads();

    float p[4]; float sum = 0.f;
#pragma unroll
    for (int u = 0; u < 4; u++) {
        p[u] = val[u] ? expf(e[u] - mx) : 0.f;
        sum += p[u];
    }
    sh[tid] = sum; __syncthreads();
    for (int s = 128; s > 0; s >>= 1) {
        if (tid < s) sh[tid] += sh[tid + s];
        __syncthreads();
    }
    float inv = 1.0f / sh[0];
#pragma unroll
    for (int u = 0; u < 4; u++) row[tid + u * 256] = p[u] * inv;
}

// ---------------------------------------------------------------------------
// AV: O[b,i,h*64+d] = sum_j P[bh,i,j] * v[b,j,h,d]
// ---------------------------------------------------------------------------
__global__ void av_kernel(const float* __restrict__ E, const float* __restrict__ qkv,
                          float* __restrict__ O) {
    int z = blockIdx.z; int b = z >> 4; int h = z & 15;
    int it = blockIdx.y; int i0 = it * 64;
    __shared__ float As[16][68];
    __shared__ float Vs[16][64];
    int tid = threadIdx.x;
    int tx = tid & 15, ty = tid >> 4;
    const float* Eb = E + (size_t)z * TT * TT;
    const float* vb = qkv + (size_t)b * TT * 3 * DD + 2 * DD + h * DHH;
    float acc[4][4] = {};
    int kmax = i0 + 64;
    for (int k0 = 0; k0 < kmax; k0 += 16) {
#pragma unroll
        for (int i2 = tid; i2 < 1024; i2 += 256) {
            int r = i2 >> 4, c = i2 & 15;
            As[c][r] = Eb[(size_t)(i0 + r) * TT + k0 + c];
        }
#pragma unroll
        for (int i2 = tid; i2 < 1024; i2 += 256) {
            int r = i2 >> 6, c = i2 & 63;
            Vs[r][c] = vb[(size_t)(k0 + r) * (3 * DD) + c];
        }
        __syncthreads();
#pragma unroll
        for (int k = 0; k < 16; k++) {
            float ra[4], rb[4];
#pragma unroll
            for (int a = 0; a < 4; a++) ra[a] = As[k][ty * 4 + a];
#pragma unroll
            for (int b2 = 0; b2 < 4; b2++) rb[b2] = Vs[k][tx * 4 + b2];
#pragma unroll
            for (int a = 0; a < 4; a++)
#pragma unroll
                for (int b2 = 0; b2 < 4; b2++)
                    acc[a][b2] += ra[a] * rb[b2];
        }
        __syncthreads();
    }
    float* ob = O + (size_t)b * TT * DD + h * DHH;
#pragma unroll
    for (int a = 0; a < 4; a++)
#pragma unroll
        for (int b2 = 0; b2 < 4; b2++)
            ob[(size_t)(i0 + ty * 4 + a) * DD + tx * 4 + b2] = acc[a][b2];
}

// ---------------------------------------------------------------------------
extern "C" void kernel_launch(void* const* d_in, const int* in_sizes, int n_in,
                              void* d_out, int out_size) {
    const float* x_in    = (const float*)d_in[0];
    const float* m       = (const float*)d_in[1];
    const int*   l       = (const int*)d_in[2];
    const float* Wqkv    = (const float*)d_in[3];
    const float* Wout    = (const float*)d_in[4];
    const float* bout    = (const float*)d_in[5];
    const float* ad_attn = (const float*)d_in[6];
    const float* ad_ffn  = (const float*)d_in[7];
    const float* W1      = (const float*)d_in[8];
    const float* b1      = (const float*)d_in[9];
    const float* W2      = (const float*)d_in[10];
    const float* b2      = (const float*)d_in[11];
    float* x = (float*)d_out;   // residual stream lives in d_out

    float *h, *qkv, *attn, *f1, *scores;
    cudaGetSymbolAddress((void**)&h,      g_h);
    cudaGetSymbolAddress((void**)&qkv,    g_qkv);
    cudaGetSymbolAddress((void**)&attn,   g_attn);
    cudaGetSymbolAddress((void**)&f1,     g_f1);
    cudaGetSymbolAddress((void**)&scores, g_scores);

    cudaMemcpyAsync(x, x_in, sizeof(float) * (size_t)NROWS * DD,
                    cudaMemcpyDeviceToDevice);

    for (int i = 0; i < NLAY; i++) {
        // attention sub-block
        adaln_kernel<<<NROWS, 256>>>(x, m, l, ad_attn + (size_t)i * NLEV * 2 * DD, h);
        gemm_tf32<0><<<dim3(3 * DD / 128, NROWS / 128), 256>>>(
            h, Wqkv + (size_t)i * DD * 3 * DD, nullptr, nullptr, nullptr,
            qkv, NROWS, 3 * DD, DD);
        scores_kernel<<<dim3(TT / 64, TT / 64, BB * HH), 256>>>(qkv, scores);
        softmax_kernel<<<dim3(TT, BB * HH), 256>>>(m, scores);
        av_kernel<<<dim3(1, TT / 64, BB * HH), 256>>>(scores, qkv, attn);
        gemm_tf32<2><<<dim3(DD / 128, NROWS / 128), 256>>>(
            attn, Wout + (size_t)i * DD * DD, bout + (size_t)i * DD, x, m,
            x, NROWS, DD, DD);
        // FFN sub-block
        adaln_kernel<<<NROWS, 256>>>(x, m, l, ad_ffn + (size_t)i * NLEV * 2 * DD, h);
        gemm_tf32<1><<<dim3(DFF / 128, NROWS / 128), 256>>>(
            h, W1 + (size_t)i * DD * DFF, b1 + (size_t)i * DFF, nullptr, nullptr,
            f1, NROWS, DFF, DD);
        gemm_tf32<2><<<dim3(DD / 128, NROWS / 128), 256>>>(
            f1, W2 + (size_t)i * DFF * DD, b2 + (size_t)i * DD, x, m,
            x, NROWS, DD, DFF);
    }
}

// round 5
// speedup vs baseline: 3.3296x; 1.9449x over previous
#include <cuda_runtime.h>
#include <math.h>
#include <stdint.h>

// Problem constants
#define BB    2
#define TT    1024
#define DD    1024
#define HH    16
#define DHH   64
#define NLAY  4
#define NLEV  8
#define DFF   4096
#define NROWS (BB*TT)
#define FMAXV 3.402823466e38f

// Scratch (device globals — no allocation allowed)
__device__ float g_h[NROWS * DD];
__device__ float g_qkv[NROWS * 3 * DD];
__device__ float g_attn[NROWS * DD];
__device__ float g_f1[NROWS * DFF];

__device__ __forceinline__ float gelu_exact(float x) {
    return 0.5f * x * (1.0f + erff(x * 0.70710678118654752f));
}

__device__ __forceinline__ float cvt_tf32(float x) {
    uint32_t u;
    asm("cvt.rna.tf32.f32 %0, %1;" : "=r"(u) : "f"(x));
    return __uint_as_float(u);
}

// ---------------------------------------------------------------------------
// AdaLN
// ---------------------------------------------------------------------------
__global__ void adaln_kernel(const float* __restrict__ x, const float* __restrict__ m,
                             const int* __restrict__ l, const float* __restrict__ emb,
                             float* __restrict__ out) {
    int row = blockIdx.x;
    int b = row / TT;
    float mv = m[row];
    const float* xr = x + (size_t)row * DD;
    float* orow = out + (size_t)row * DD;
    int tid = threadIdx.x;

    float v[4];
    float s = 0.f, ss = 0.f;
#pragma unroll
    for (int u = 0; u < 4; u++) {
        v[u] = xr[tid + u * 256];
        s += v[u];
        ss += v[u] * v[u];
    }
    __shared__ float sh1[256];
    __shared__ float sh2[256];
    sh1[tid] = s; sh2[tid] = ss;
    __syncthreads();
    for (int stp = 128; stp > 0; stp >>= 1) {
        if (tid < stp) { sh1[tid] += sh1[tid + stp]; sh2[tid] += sh2[tid + stp]; }
        __syncthreads();
    }
    float mu  = sh1[0] * (1.0f / DD);
    float var = sh2[0] * (1.0f / DD) - mu * mu;
    float rinv = rsqrtf(var + 1e-5f);

    const float* g = emb + (size_t)l[b] * (2 * DD);
#pragma unroll
    for (int u = 0; u < 4; u++) {
        int d = tid + u * 256;
        float hn = (v[u] - mu) * rinv;
        float h = 2.0f * (1.0f - 0.1f * hn) * hn;
        orow[d] = (expf(g[d]) * h + g[DD + d]) * mv;
    }
}

// ---------------------------------------------------------------------------
// tf32 tensor-core GEMM: C = epi(A @ W + bias)
// EPI: 0 = none, 1 = GELU, 2 = residual+mask  C = (res + gemm + bias)*m[row]
// ---------------------------------------------------------------------------
template <int EPI>
__global__ void __launch_bounds__(256)
gemm_tf32(const float* __restrict__ A, const float* __restrict__ W,
          const float* __restrict__ bias, const float* __restrict__ res,
          const float* __restrict__ m, float* __restrict__ C,
          int M, int N, int K) {
    __shared__ __align__(16) float As[128][36];
    __shared__ __align__(16) float Bs[32][136];

    int tid  = threadIdx.x;
    int warp = tid >> 5, lane = tid & 31;
    int g = lane >> 2, t = lane & 3;
    int warpm = warp >> 2, warpn = warp & 3;
    int row0 = blockIdx.y * 128, col0 = blockIdx.x * 128;

    float acc[4][4][4] = {};

    for (int k0 = 0; k0 < K; k0 += 32) {
#pragma unroll
        for (int i = 0; i < 4; i++) {
            int idx = tid + i * 256;
            int r = idx >> 3, c4 = (idx & 7) * 4;
            float4 v = *(const float4*)(A + (size_t)(row0 + r) * K + k0 + c4);
            float4 w;
            w.x = cvt_tf32(v.x); w.y = cvt_tf32(v.y);
            w.z = cvt_tf32(v.z); w.w = cvt_tf32(v.w);
            *(float4*)&As[r][c4] = w;
        }
#pragma unroll
        for (int i = 0; i < 4; i++) {
            int idx = tid + i * 256;
            int r = idx >> 5, c4 = (idx & 31) * 4;
            float4 v = *(const float4*)(W + (size_t)(k0 + r) * N + col0 + c4);
            float4 w;
            w.x = cvt_tf32(v.x); w.y = cvt_tf32(v.y);
            w.z = cvt_tf32(v.z); w.w = cvt_tf32(v.w);
            *(float4*)&Bs[r][c4] = w;
        }
        __syncthreads();

#pragma unroll
        for (int kk = 0; kk < 32; kk += 8) {
            uint32_t af[4][4], bf[4][2];
#pragma unroll
            for (int mi = 0; mi < 4; mi++) {
                int rb = warpm * 64 + mi * 16 + g;
                af[mi][0] = __float_as_uint(As[rb    ][kk + t    ]);
                af[mi][1] = __float_as_uint(As[rb + 8][kk + t    ]);
                af[mi][2] = __float_as_uint(As[rb    ][kk + t + 4]);
                af[mi][3] = __float_as_uint(As[rb + 8][kk + t + 4]);
            }
#pragma unroll
            for (int ni = 0; ni < 4; ni++) {
                int cb = warpn * 32 + ni * 8 + g;
                bf[ni][0] = __float_as_uint(Bs[kk + t    ][cb]);
                bf[ni][1] = __float_as_uint(Bs[kk + t + 4][cb]);
            }
#pragma unroll
            for (int mi = 0; mi < 4; mi++)
#pragma unroll
                for (int ni = 0; ni < 4; ni++) {
                    asm volatile(
                        "mma.sync.aligned.m16n8k8.row.col.f32.tf32.tf32.f32 "
                        "{%0,%1,%2,%3}, {%4,%5,%6,%7}, {%8,%9}, {%0,%1,%2,%3};"
                        : "+f"(acc[mi][ni][0]), "+f"(acc[mi][ni][1]),
                          "+f"(acc[mi][ni][2]), "+f"(acc[mi][ni][3])
                        : "r"(af[mi][0]), "r"(af[mi][1]), "r"(af[mi][2]), "r"(af[mi][3]),
                          "r"(bf[ni][0]), "r"(bf[ni][1]));
                }
        }
        __syncthreads();
    }

#pragma unroll
    for (int mi = 0; mi < 4; mi++) {
        int r0 = row0 + warpm * 64 + mi * 16 + g;
        int r1 = r0 + 8;
        float m0 = (EPI == 2) ? m[r0] : 0.f;
        float m1 = (EPI == 2) ? m[r1] : 0.f;
#pragma unroll
        for (int ni = 0; ni < 4; ni++) {
            int cb = col0 + warpn * 32 + ni * 8 + 2 * t;
            float v0 = acc[mi][ni][0], v1 = acc[mi][ni][1];
            float v2 = acc[mi][ni][2], v3 = acc[mi][ni][3];
            if (bias) {
                float b0 = bias[cb], b1 = bias[cb + 1];
                v0 += b0; v1 += b1; v2 += b0; v3 += b1;
            }
            if (EPI == 1) {
                v0 = gelu_exact(v0); v1 = gelu_exact(v1);
                v2 = gelu_exact(v2); v3 = gelu_exact(v3);
            }
            if (EPI == 2) {
                const float* rr0 = res + (size_t)r0 * N + cb;
                const float* rr1 = res + (size_t)r1 * N + cb;
                v0 = (rr0[0] + v0) * m0; v1 = (rr0[1] + v1) * m0;
                v2 = (rr1[0] + v2) * m1; v3 = (rr1[1] + v3) * m1;
            }
            *(float2*)(C + (size_t)r0 * N + cb) = make_float2(v0, v1);
            *(float2*)(C + (size_t)r1 * N + cb) = make_float2(v2, v3);
        }
    }
}

// ---------------------------------------------------------------------------
// Flash attention (tf32 MMA), FIXED warp ownership:
// 8 warps; warp w owns S/P/O rows [w*16, w*16+16) across ALL 64 j-columns,
// so online-softmax row state is consistent within one warp.
// smem: Q[128][68] | K[64][68] | V[64][68] | P[128][68]
// ---------------------------------------------------------------------------
#define FA_SMEM ((128*68 + 64*68 + 64*68 + 128*68) * 4)

__global__ void __launch_bounds__(256)
flash_kernel(const float* __restrict__ qkv, const float* __restrict__ mk,
             float* __restrict__ O) {
    extern __shared__ float sm[];
    float (*Qs)[68] = (float(*)[68])sm;
    float (*Ks)[68] = (float(*)[68])(sm + 128 * 68);
    float (*Vs)[68] = (float(*)[68])(sm + 128 * 68 + 64 * 68);
    float (*Ps)[68] = (float(*)[68])(sm + 128 * 68 + 2 * 64 * 68);

    int z = blockIdx.y; int b = z >> 4; int h = z & 15;
    int it = gridDim.x - 1 - blockIdx.x;        // heavy tiles first
    int i0 = it * 128;
    int tid = threadIdx.x;
    int warp = tid >> 5, lane = tid & 31;
    int g = lane >> 2, t = lane & 3;
    int wrow = warp * 16;                       // warp's row stripe in the tile

    const float* qb = qkv + (size_t)b * TT * 3 * DD + h * DHH;
    const float* kb = qb + DD;
    const float* vb = qb + 2 * DD;
    const float* mrow = mk + b * TT;

    // load Q tile (tf32-converted)
#pragma unroll
    for (int i = 0; i < 8; i++) {
        int idx = tid + i * 256;
        int r = idx >> 4, c4 = (idx & 15) * 4;
        float4 v = *(const float4*)(qb + (size_t)(i0 + r) * (3 * DD) + c4);
        float4 w;
        w.x = cvt_tf32(v.x); w.y = cvt_tf32(v.y);
        w.z = cvt_tf32(v.z); w.w = cvt_tf32(v.w);
        *(float4*)&Qs[r][c4] = w;
    }

    float oacc[8][4] = {};
    float mst0 = -FMAXV, mst1 = -FMAXV;   // row g, row g+8
    float lst0 = 0.f,    lst1 = 0.f;

    int jend = i0 + 128;
    for (int j0 = 0; j0 < jend; j0 += 64) {
        __syncthreads();                  // prev PV done with Ks/Vs
        // load K,V j-tile
#pragma unroll
        for (int i = 0; i < 4; i++) {
            int idx = tid + i * 256;
            int r = idx >> 4, c4 = (idx & 15) * 4;
            float4 kv = *(const float4*)(kb + (size_t)(j0 + r) * (3 * DD) + c4);
            float4 w;
            w.x = cvt_tf32(kv.x); w.y = cvt_tf32(kv.y);
            w.z = cvt_tf32(kv.z); w.w = cvt_tf32(kv.w);
            *(float4*)&Ks[r][c4] = w;
            float4 vv = *(const float4*)(vb + (size_t)(j0 + r) * (3 * DD) + c4);
            float4 u;
            u.x = cvt_tf32(vv.x); u.y = cvt_tf32(vv.y);
            u.z = cvt_tf32(vv.z); u.w = cvt_tf32(vv.w);
            *(float4*)&Vs[r][c4] = u;
        }
        __syncthreads();

        // S = Q @ K^T : warp computes 16 x 64
        float sacc[8][4] = {};
#pragma unroll
        for (int kk = 0; kk < 64; kk += 8) {
            uint32_t af[4], bf[8][2];
            af[0] = __float_as_uint(Qs[wrow + g    ][kk + t    ]);
            af[1] = __float_as_uint(Qs[wrow + g + 8][kk + t    ]);
            af[2] = __float_as_uint(Qs[wrow + g    ][kk + t + 4]);
            af[3] = __float_as_uint(Qs[wrow + g + 8][kk + t + 4]);
#pragma unroll
            for (int ni = 0; ni < 8; ni++) {
                int cb = ni * 8 + g;
                bf[ni][0] = __float_as_uint(Ks[cb][kk + t    ]);   // K^T
                bf[ni][1] = __float_as_uint(Ks[cb][kk + t + 4]);
            }
#pragma unroll
            for (int ni = 0; ni < 8; ni++) {
                asm volatile(
                    "mma.sync.aligned.m16n8k8.row.col.f32.tf32.tf32.f32 "
                    "{%0,%1,%2,%3}, {%4,%5,%6,%7}, {%8,%9}, {%0,%1,%2,%3};"
                    : "+f"(sacc[ni][0]), "+f"(sacc[ni][1]),
                      "+f"(sacc[ni][2]), "+f"(sacc[ni][3])
                    : "r"(af[0]), "r"(af[1]), "r"(af[2]), "r"(af[3]),
                      "r"(bf[ni][0]), "r"(bf[ni][1]));
            }
        }

        // scale + mask
        int row0 = i0 + wrow + g;
        int row1 = row0 + 8;
#pragma unroll
        for (int ni = 0; ni < 8; ni++) {
            int j = j0 + ni * 8 + 2 * t;
            float km0 = mrow[j], km1 = mrow[j + 1];
            bool ok00 = (j     <= row0) && (km0 != 0.f);
            bool ok01 = (j + 1 <= row0) && (km1 != 0.f);
            bool ok10 = (j     <= row1) && (km0 != 0.f);
            bool ok11 = (j + 1 <= row1) && (km1 != 0.f);
            sacc[ni][0] = ok00 ? sacc[ni][0] * 0.125f : -FMAXV;
            sacc[ni][1] = ok01 ? sacc[ni][1] * 0.125f : -FMAXV;
            sacc[ni][2] = ok10 ? sacc[ni][2] * 0.125f : -FMAXV;
            sacc[ni][3] = ok11 ? sacc[ni][3] * 0.125f : -FMAXV;
        }

        // full-row maxes within the warp (quad shuffle over t)
        float mx0 = -FMAXV, mx1 = -FMAXV;
#pragma unroll
        for (int ni = 0; ni < 8; ni++) {
            mx0 = fmaxf(mx0, fmaxf(sacc[ni][0], sacc[ni][1]));
            mx1 = fmaxf(mx1, fmaxf(sacc[ni][2], sacc[ni][3]));
        }
        mx0 = fmaxf(mx0, __shfl_xor_sync(0xffffffff, mx0, 1));
        mx0 = fmaxf(mx0, __shfl_xor_sync(0xffffffff, mx0, 2));
        mx1 = fmaxf(mx1, __shfl_xor_sync(0xffffffff, mx1, 1));
        mx1 = fmaxf(mx1, __shfl_xor_sync(0xffffffff, mx1, 2));

        float nm0 = fmaxf(mst0, mx0);
        float nm1 = fmaxf(mst1, mx1);
        float a0 = expf(mst0 - nm0);
        float a1 = expf(mst1 - nm1);
        mst0 = nm0; mst1 = nm1;

        float rs0 = 0.f, rs1 = 0.f;
#pragma unroll
        for (int ni = 0; ni < 8; ni++) {
            float p0 = expf(sacc[ni][0] - nm0);
            float p1 = expf(sacc[ni][1] - nm0);
            float p2 = expf(sacc[ni][2] - nm1);
            float p3 = expf(sacc[ni][3] - nm1);
            sacc[ni][0] = p0; sacc[ni][1] = p1;
            sacc[ni][2] = p2; sacc[ni][3] = p3;
            rs0 += p0 + p1; rs1 += p2 + p3;
        }
        rs0 += __shfl_xor_sync(0xffffffff, rs0, 1);
        rs0 += __shfl_xor_sync(0xffffffff, rs0, 2);
        rs1 += __shfl_xor_sync(0xffffffff, rs1, 1);
        rs1 += __shfl_xor_sync(0xffffffff, rs1, 2);
        lst0 = lst0 * a0 + rs0;
        lst1 = lst1 * a1 + rs1;

        // rescale O
#pragma unroll
        for (int ni = 0; ni < 8; ni++) {
            oacc[ni][0] *= a0; oacc[ni][1] *= a0;
            oacc[ni][2] *= a1; oacc[ni][3] *= a1;
        }

        // write P (tf32) to warp-local smem rows, re-fragment
#pragma unroll
        for (int ni = 0; ni < 8; ni++) {
            int lc = ni * 8 + 2 * t;
            Ps[wrow + g    ][lc]     = cvt_tf32(sacc[ni][0]);
            Ps[wrow + g    ][lc + 1] = cvt_tf32(sacc[ni][1]);
            Ps[wrow + g + 8][lc]     = cvt_tf32(sacc[ni][2]);
            Ps[wrow + g + 8][lc + 1] = cvt_tf32(sacc[ni][3]);
        }
        __syncwarp();

        // O += P @ V : 16 x 64, k = 64 (j)
#pragma unroll
        for (int kk = 0; kk < 64; kk += 8) {
            uint32_t af[4], bf[8][2];
            af[0] = __float_as_uint(Ps[wrow + g    ][kk + t    ]);
            af[1] = __float_as_uint(Ps[wrow + g + 8][kk + t    ]);
            af[2] = __float_as_uint(Ps[wrow + g    ][kk + t + 4]);
            af[3] = __float_as_uint(Ps[wrow + g + 8][kk + t + 4]);
#pragma unroll
            for (int ni = 0; ni < 8; ni++) {
                int cb = ni * 8 + g;
                bf[ni][0] = __float_as_uint(Vs[kk + t    ][cb]);
                bf[ni][1] = __float_as_uint(Vs[kk + t + 4][cb]);
            }
#pragma unroll
            for (int ni = 0; ni < 8; ni++) {
                asm volatile(
                    "mma.sync.aligned.m16n8k8.row.col.f32.tf32.tf32.f32 "
                    "{%0,%1,%2,%3}, {%4,%5,%6,%7}, {%8,%9}, {%0,%1,%2,%3};"
                    : "+f"(oacc[ni][0]), "+f"(oacc[ni][1]),
                      "+f"(oacc[ni][2]), "+f"(oacc[ni][3])
                    : "r"(af[0]), "r"(af[1]), "r"(af[2]), "r"(af[3]),
                      "r"(bf[ni][0]), "r"(bf[ni][1]));
            }
        }
    }

    // epilogue: O / l -> g_attn[b, i, h*64+d]
    float* ob = O + (size_t)b * TT * DD + h * DHH;
    int r0 = i0 + wrow + g;
    int r1 = r0 + 8;
    float inv0 = (lst0 > 0.f) ? 1.0f / lst0 : 0.f;
    float inv1 = (lst1 > 0.f) ? 1.0f / lst1 : 0.f;
#pragma unroll
    for (int ni = 0; ni < 8; ni++) {
        int cb = ni * 8 + 2 * t;
        *(float2*)(ob + (size_t)r0 * DD + cb) =
            make_float2(oacc[ni][0] * inv0, oacc[ni][1] * inv0);
        *(float2*)(ob + (size_t)r1 * DD + cb) =
            make_float2(oacc[ni][2] * inv1, oacc[ni][3] * inv1);
    }
}

// ---------------------------------------------------------------------------
extern "C" void kernel_launch(void* const* d_in, const int* in_sizes, int n_in,
                              void* d_out, int out_size) {
    const float* x_in    = (const float*)d_in[0];
    const float* m       = (const float*)d_in[1];
    const int*   l       = (const int*)d_in[2];
    const float* Wqkv    = (const float*)d_in[3];
    const float* Wout    = (const float*)d_in[4];
    const float* bout    = (const float*)d_in[5];
    const float* ad_attn = (const float*)d_in[6];
    const float* ad_ffn  = (const float*)d_in[7];
    const float* W1      = (const float*)d_in[8];
    const float* b1      = (const float*)d_in[9];
    const float* W2      = (const float*)d_in[10];
    const float* b2      = (const float*)d_in[11];
    float* x = (float*)d_out;

    float *h, *qkv, *attn, *f1;
    cudaGetSymbolAddress((void**)&h,    g_h);
    cudaGetSymbolAddress((void**)&qkv,  g_qkv);
    cudaGetSymbolAddress((void**)&attn, g_attn);
    cudaGetSymbolAddress((void**)&f1,   g_f1);

    cudaFuncSetAttribute(flash_kernel,
                         cudaFuncAttributeMaxDynamicSharedMemorySize, FA_SMEM);

    cudaMemcpyAsync(x, x_in, sizeof(float) * (size_t)NROWS * DD,
                    cudaMemcpyDeviceToDevice);

    for (int i = 0; i < NLAY; i++) {
        // attention sub-block
        adaln_kernel<<<NROWS, 256>>>(x, m, l, ad_attn + (size_t)i * NLEV * 2 * DD, h);
        gemm_tf32<0><<<dim3(3 * DD / 128, NROWS / 128), 256>>>(
            h, Wqkv + (size_t)i * DD * 3 * DD, nullptr, nullptr, nullptr,
            qkv, NROWS, 3 * DD, DD);
        flash_kernel<<<dim3(TT / 128, BB * HH), 256, FA_SMEM>>>(qkv, m, attn);
        gemm_tf32<2><<<dim3(DD / 128, NROWS / 128), 256>>>(
            attn, Wout + (size_t)i * DD * DD, bout + (size_t)i * DD, x, m,
            x, NROWS, DD, DD);
        // FFN sub-block
        adaln_kernel<<<NROWS, 256>>>(x, m, l, ad_ffn + (size_t)i * NLEV * 2 * DD, h);
        gemm_tf32<1><<<dim3(DFF / 128, NROWS / 128), 256>>>(
            h, W1 + (size_t)i * DD * DFF, b1 + (size_t)i * DFF, nullptr, nullptr,
            f1, NROWS, DFF, DD);
        gemm_tf32<2><<<dim3(DD / 128, NROWS / 128), 256>>>(
            f1, W2 + (size_t)i * DFF * DD, b2 + (size_t)i * DD, x, m,
            x, NROWS, DD, DFF);
    }
}

// round 7
// speedup vs baseline: 4.0566x; 1.2183x over previous
#include <cuda_runtime.h>
#include <math.h>
#include <stdint.h>

// Problem constants
#define BB    2
#define TT    1024
#define DD    1024
#define HH    16
#define DHH   64
#define NLAY  4
#define NLEV  8
#define DFF   4096
#define NROWS (BB*TT)
#define FMAXV 3.402823466e38f

// Scratch (device globals — no allocation allowed)
__device__ float g_h[NROWS * DD];
__device__ float g_qkv[NROWS * 3 * DD];
__device__ float g_attn[NROWS * DD];
__device__ float g_f1[NROWS * DFF];

__device__ __forceinline__ float gelu_exact(float x) {
    return 0.5f * x * (1.0f + erff(x * 0.70710678118654752f));
}

__device__ __forceinline__ float cvt_tf32(float x) {
    uint32_t u;
    asm("cvt.rna.tf32.f32 %0, %1;" : "=r"(u) : "f"(x));
    return __uint_as_float(u);
}

__device__ __forceinline__ uint32_t cvt_tf32_u(float x) {
    uint32_t u;
    asm("cvt.rna.tf32.f32 %0, %1;" : "=r"(u) : "f"(x));
    return u;
}

__device__ __forceinline__ void cp_async16(void* smem, const void* gmem) {
    uint32_t s = (uint32_t)__cvta_generic_to_shared(smem);
    asm volatile("cp.async.cg.shared.global [%0], [%1], 16;" :: "r"(s), "l"(gmem));
}

// ---------------------------------------------------------------------------
// AdaLN
// ---------------------------------------------------------------------------
__global__ void adaln_kernel(const float* __restrict__ x, const float* __restrict__ m,
                             const int* __restrict__ l, const float* __restrict__ emb,
                             float* __restrict__ out) {
    int row = blockIdx.x;
    int b = row / TT;
    float mv = m[row];
    const float* xr = x + (size_t)row * DD;
    float* orow = out + (size_t)row * DD;
    int tid = threadIdx.x;

    float v[4];
    float s = 0.f, ss = 0.f;
#pragma unroll
    for (int u = 0; u < 4; u++) {
        v[u] = xr[tid + u * 256];
        s += v[u];
        ss += v[u] * v[u];
    }
    __shared__ float sh1[256];
    __shared__ float sh2[256];
    sh1[tid] = s; sh2[tid] = ss;
    __syncthreads();
    for (int stp = 128; stp > 0; stp >>= 1) {
        if (tid < stp) { sh1[tid] += sh1[tid + stp]; sh2[tid] += sh2[tid + stp]; }
        __syncthreads();
    }
    float mu  = sh1[0] * (1.0f / DD);
    float var = sh2[0] * (1.0f / DD) - mu * mu;
    float rinv = rsqrtf(var + 1e-5f);

    const float* g = emb + (size_t)l[b] * (2 * DD);
#pragma unroll
    for (int u = 0; u < 4; u++) {
        int d = tid + u * 256;
        float hn = (v[u] - mu) * rinv;
        float h = 2.0f * (1.0f - 0.1f * hn) * hn;
        orow[d] = (expf(g[d]) * h + g[DD + d]) * mv;
    }
}

// ---------------------------------------------------------------------------
// tf32 tensor-core GEMM, 2-stage cp.async pipeline: C = epi(A @ W + bias)
// EPI: 0 = none, 1 = GELU, 2 = residual+mask  C = (res + gemm + bias)*m[row]
// ---------------------------------------------------------------------------
template <int EPI>
__global__ void __launch_bounds__(256, 2)
gemm_tf32(const float* __restrict__ A, const float* __restrict__ W,
          const float* __restrict__ bias, const float* __restrict__ res,
          const float* __restrict__ m, float* __restrict__ C,
          int M, int N, int K) {
    __shared__ __align__(16) float As[2][128][36];
    __shared__ __align__(16) float Bs[2][32][136];

    int tid  = threadIdx.x;
    int warp = tid >> 5, lane = tid & 31;
    int g = lane >> 2, t = lane & 3;
    int warpm = warp >> 2, warpn = warp & 3;
    int row0 = blockIdx.y * 128, col0 = blockIdx.x * 128;

    float acc[4][4][4] = {};

    // per-thread load coordinates
    int ar = tid >> 3, ac4 = (tid & 7) * 4;       // + i*32 rows
    int br = tid >> 5, bc4 = (tid & 31) * 4;      // + i*8 rows

#define ISSUE_TILE(buf, k0)                                                     \
    {                                                                           \
        _Pragma("unroll")                                                       \
        for (int i = 0; i < 4; i++)                                             \
            cp_async16(&As[buf][ar + i * 32][ac4],                              \
                       A + (size_t)(row0 + ar + i * 32) * K + (k0) + ac4);      \
        _Pragma("unroll")                                                       \
        for (int i = 0; i < 4; i++)                                             \
            cp_async16(&Bs[buf][br + i * 8][bc4],                               \
                       W + (size_t)((k0) + br + i * 8) * N + col0 + bc4);       \
        asm volatile("cp.async.commit_group;");                                 \
    }

    ISSUE_TILE(0, 0)
    ISSUE_TILE(1, 32)

    int buf = 0;
    for (int k0 = 0; k0 < K; k0 += 32) {
        if (k0 + 32 < K) {
            asm volatile("cp.async.wait_group 1;");
        } else {
            asm volatile("cp.async.wait_group 0;");
        }
        __syncthreads();

#pragma unroll
        for (int kk = 0; kk < 32; kk += 8) {
            uint32_t af[4][4], bf[4][2];
#pragma unroll
            for (int mi = 0; mi < 4; mi++) {
                int rb = warpm * 64 + mi * 16 + g;
                af[mi][0] = cvt_tf32_u(As[buf][rb    ][kk + t    ]);
                af[mi][1] = cvt_tf32_u(As[buf][rb + 8][kk + t    ]);
                af[mi][2] = cvt_tf32_u(As[buf][rb    ][kk + t + 4]);
                af[mi][3] = cvt_tf32_u(As[buf][rb + 8][kk + t + 4]);
            }
#pragma unroll
            for (int ni = 0; ni < 4; ni++) {
                int cb = warpn * 32 + ni * 8 + g;
                bf[ni][0] = cvt_tf32_u(Bs[buf][kk + t    ][cb]);
                bf[ni][1] = cvt_tf32_u(Bs[buf][kk + t + 4][cb]);
            }
#pragma unroll
            for (int mi = 0; mi < 4; mi++)
#pragma unroll
                for (int ni = 0; ni < 4; ni++) {
                    asm volatile(
                        "mma.sync.aligned.m16n8k8.row.col.f32.tf32.tf32.f32 "
                        "{%0,%1,%2,%3}, {%4,%5,%6,%7}, {%8,%9}, {%0,%1,%2,%3};"
                        : "+f"(acc[mi][ni][0]), "+f"(acc[mi][ni][1]),
                          "+f"(acc[mi][ni][2]), "+f"(acc[mi][ni][3])
                        : "r"(af[mi][0]), "r"(af[mi][1]), "r"(af[mi][2]), "r"(af[mi][3]),
                          "r"(bf[ni][0]), "r"(bf[ni][1]));
                }
        }
        __syncthreads();
        if (k0 + 64 < K) {
            ISSUE_TILE(buf, k0 + 64)
        }
        buf ^= 1;
    }
#undef ISSUE_TILE

#pragma unroll
    for (int mi = 0; mi < 4; mi++) {
        int r0 = row0 + warpm * 64 + mi * 16 + g;
        int r1 = r0 + 8;
        float m0 = (EPI == 2) ? m[r0] : 0.f;
        float m1 = (EPI == 2) ? m[r1] : 0.f;
#pragma unroll
        for (int ni = 0; ni < 4; ni++) {
            int cb = col0 + warpn * 32 + ni * 8 + 2 * t;
            float v0 = acc[mi][ni][0], v1 = acc[mi][ni][1];
            float v2 = acc[mi][ni][2], v3 = acc[mi][ni][3];
            if (bias) {
                float b0 = bias[cb], b1 = bias[cb + 1];
                v0 += b0; v1 += b1; v2 += b0; v3 += b1;
            }
            if (EPI == 1) {
                v0 = gelu_exact(v0); v1 = gelu_exact(v1);
                v2 = gelu_exact(v2); v3 = gelu_exact(v3);
            }
            if (EPI == 2) {
                const float* rr0 = res + (size_t)r0 * N + cb;
                const float* rr1 = res + (size_t)r1 * N + cb;
                v0 = (rr0[0] + v0) * m0; v1 = (rr0[1] + v1) * m0;
                v2 = (rr1[0] + v2) * m1; v3 = (rr1[1] + v3) * m1;
            }
            *(float2*)(C + (size_t)r0 * N + cb) = make_float2(v0, v1);
            *(float2*)(C + (size_t)r1 * N + cb) = make_float2(v2, v3);
        }
    }
}

// ---------------------------------------------------------------------------
// Flash attention (tf32 MMA): 8 warps; warp w owns rows [w*16, w*16+16)
// across all 64 j-columns. Online softmax state is warp-consistent.
// smem: Q[128][68] | K[64][68] | V[64][68] | P[128][68]
// ---------------------------------------------------------------------------
#define FA_SMEM ((128*68 + 64*68 + 64*68 + 128*68) * 4)

__global__ void __launch_bounds__(256)
flash_kernel(const float* __restrict__ qkv, const float* __restrict__ mk,
             float* __restrict__ O) {
    extern __shared__ float sm[];
    float (*Qs)[68] = (float(*)[68])sm;
    float (*Ks)[68] = (float(*)[68])(sm + 128 * 68);
    float (*Vs)[68] = (float(*)[68])(sm + 128 * 68 + 64 * 68);
    float (*Ps)[68] = (float(*)[68])(sm + 128 * 68 + 2 * 64 * 68);

    int z = blockIdx.y; int b = z >> 4; int h = z & 15;
    int it = gridDim.x - 1 - blockIdx.x;        // heavy tiles first
    int i0 = it * 128;
    int tid = threadIdx.x;
    int warp = tid >> 5, lane = tid & 31;
    int g = lane >> 2, t = lane & 3;
    int wrow = warp * 16;

    const float* qb = qkv + (size_t)b * TT * 3 * DD + h * DHH;
    const float* kb = qb + DD;
    const float* vb = qb + 2 * DD;
    const float* mrow = mk + b * TT;

#pragma unroll
    for (int i = 0; i < 8; i++) {
        int idx = tid + i * 256;
        int r = idx >> 4, c4 = (idx & 15) * 4;
        float4 v = *(const float4*)(qb + (size_t)(i0 + r) * (3 * DD) + c4);
        float4 w;
        w.x = cvt_tf32(v.x); w.y = cvt_tf32(v.y);
        w.z = cvt_tf32(v.z); w.w = cvt_tf32(v.w);
        *(float4*)&Qs[r][c4] = w;
    }

    float oacc[8][4] = {};
    float mst0 = -FMAXV, mst1 = -FMAXV;
    float lst0 = 0.f,    lst1 = 0.f;

    int jend = i0 + 128;
    for (int j0 = 0; j0 < jend; j0 += 64) {
        __syncthreads();
#pragma unroll
        for (int i = 0; i < 4; i++) {
            int idx = tid + i * 256;
            int r = idx >> 4, c4 = (idx & 15) * 4;
            float4 kv = *(const float4*)(kb + (size_t)(j0 + r) * (3 * DD) + c4);
            float4 w;
            w.x = cvt_tf32(kv.x); w.y = cvt_tf32(kv.y);
            w.z = cvt_tf32(kv.z); w.w = cvt_tf32(kv.w);
            *(float4*)&Ks[r][c4] = w;
            float4 vv = *(const float4*)(vb + (size_t)(j0 + r) * (3 * DD) + c4);
            float4 u;
            u.x = cvt_tf32(vv.x); u.y = cvt_tf32(vv.y);
            u.z = cvt_tf32(vv.z); u.w = cvt_tf32(vv.w);
            *(float4*)&Vs[r][c4] = u;
        }
        __syncthreads();

        // S = Q @ K^T : warp computes 16 x 64
        float sacc[8][4] = {};
#pragma unroll
        for (int kk = 0; kk < 64; kk += 8) {
            uint32_t af[4], bf[8][2];
            af[0] = __float_as_uint(Qs[wrow + g    ][kk + t    ]);
            af[1] = __float_as_uint(Qs[wrow + g + 8][kk + t    ]);
            af[2] = __float_as_uint(Qs[wrow + g    ][kk + t + 4]);
            af[3] = __float_as_uint(Qs[wrow + g + 8][kk + t + 4]);
#pragma unroll
            for (int ni = 0; ni < 8; ni++) {
                int cb = ni * 8 + g;
                bf[ni][0] = __float_as_uint(Ks[cb][kk + t    ]);
                bf[ni][1] = __float_as_uint(Ks[cb][kk + t + 4]);
            }
#pragma unroll
            for (int ni = 0; ni < 8; ni++) {
                asm volatile(
                    "mma.sync.aligned.m16n8k8.row.col.f32.tf32.tf32.f32 "
                    "{%0,%1,%2,%3}, {%4,%5,%6,%7}, {%8,%9}, {%0,%1,%2,%3};"
                    : "+f"(sacc[ni][0]), "+f"(sacc[ni][1]),
                      "+f"(sacc[ni][2]), "+f"(sacc[ni][3])
                    : "r"(af[0]), "r"(af[1]), "r"(af[2]), "r"(af[3]),
                      "r"(bf[ni][0]), "r"(bf[ni][1]));
            }
        }

        int row0 = i0 + wrow + g;
        int row1 = row0 + 8;
#pragma unroll
        for (int ni = 0; ni < 8; ni++) {
            int j = j0 + ni * 8 + 2 * t;
            float km0 = mrow[j], km1 = mrow[j + 1];
            bool ok00 = (j     <= row0) && (km0 != 0.f);
            bool ok01 = (j + 1 <= row0) && (km1 != 0.f);
            bool ok10 = (j     <= row1) && (km0 != 0.f);
            bool ok11 = (j + 1 <= row1) && (km1 != 0.f);
            sacc[ni][0] = ok00 ? sacc[ni][0] * 0.125f : -FMAXV;
            sacc[ni][1] = ok01 ? sacc[ni][1] * 0.125f : -FMAXV;
            sacc[ni][2] = ok10 ? sacc[ni][2] * 0.125f : -FMAXV;
            sacc[ni][3] = ok11 ? sacc[ni][3] * 0.125f : -FMAXV;
        }

        float mx0 = -FMAXV, mx1 = -FMAXV;
#pragma unroll
        for (int ni = 0; ni < 8; ni++) {
            mx0 = fmaxf(mx0, fmaxf(sacc[ni][0], sacc[ni][1]));
            mx1 = fmaxf(mx1, fmaxf(sacc[ni][2], sacc[ni][3]));
        }
        mx0 = fmaxf(mx0, __shfl_xor_sync(0xffffffff, mx0, 1));
        mx0 = fmaxf(mx0, __shfl_xor_sync(0xffffffff, mx0, 2));
        mx1 = fmaxf(mx1, __shfl_xor_sync(0xffffffff, mx1, 1));
        mx1 = fmaxf(mx1, __shfl_xor_sync(0xffffffff, mx1, 2));

        float nm0 = fmaxf(mst0, mx0);
        float nm1 = fmaxf(mst1, mx1);
        float a0 = expf(mst0 - nm0);
        float a1 = expf(mst1 - nm1);
        mst0 = nm0; mst1 = nm1;

        float rs0 = 0.f, rs1 = 0.f;
#pragma unroll
        for (int ni = 0; ni < 8; ni++) {
            float p0 = expf(sacc[ni][0] - nm0);
            float p1 = expf(sacc[ni][1] - nm0);
            float p2 = expf(sacc[ni][2] - nm1);
            float p3 = expf(sacc[ni][3] - nm1);
            sacc[ni][0] = p0; sacc[ni][1] = p1;
            sacc[ni][2] = p2; sacc[ni][3] = p3;
            rs0 += p0 + p1; rs1 += p2 + p3;
        }
        rs0 += __shfl_xor_sync(0xffffffff, rs0, 1);
        rs0 += __shfl_xor_sync(0xffffffff, rs0, 2);
        rs1 += __shfl_xor_sync(0xffffffff, rs1, 1);
        rs1 += __shfl_xor_sync(0xffffffff, rs1, 2);
        lst0 = lst0 * a0 + rs0;
        lst1 = lst1 * a1 + rs1;

#pragma unroll
        for (int ni = 0; ni < 8; ni++) {
            oacc[ni][0] *= a0; oacc[ni][1] *= a0;
            oacc[ni][2] *= a1; oacc[ni][3] *= a1;
        }

#pragma unroll
        for (int ni = 0; ni < 8; ni++) {
            int lc = ni * 8 + 2 * t;
            Ps[wrow + g    ][lc]     = cvt_tf32(sacc[ni][0]);
            Ps[wrow + g    ][lc + 1] = cvt_tf32(sacc[ni][1]);
            Ps[wrow + g + 8][lc]     = cvt_tf32(sacc[ni][2]);
            Ps[wrow + g + 8][lc + 1] = cvt_tf32(sacc[ni][3]);
        }
        __syncwarp();

        // O += P @ V
#pragma unroll
        for (int kk = 0; kk < 64; kk += 8) {
            uint32_t af[4], bf[8][2];
            af[0] = __float_as_uint(Ps[wrow + g    ][kk + t    ]);
            af[1] = __float_as_uint(Ps[wrow + g + 8][kk + t    ]);
            af[2] = __float_as_uint(Ps[wrow + g    ][kk + t + 4]);
            af[3] = __float_as_uint(Ps[wrow + g + 8][kk + t + 4]);
#pragma unroll
            for (int ni = 0; ni < 8; ni++) {
                int cb = ni * 8 + g;
                bf[ni][0] = __float_as_uint(Vs[kk + t    ][cb]);
                bf[ni][1] = __float_as_uint(Vs[kk + t + 4][cb]);
            }
#pragma unroll
            for (int ni = 0; ni < 8; ni++) {
                asm volatile(
                    "mma.sync.aligned.m16n8k8.row.col.f32.tf32.tf32.f32 "
                    "{%0,%1,%2,%3}, {%4,%5,%6,%7}, {%8,%9}, {%0,%1,%2,%3};"
                    : "+f"(oacc[ni][0]), "+f"(oacc[ni][1]),
                      "+f"(oacc[ni][2]), "+f"(oacc[ni][3])
                    : "r"(af[0]), "r"(af[1]), "r"(af[2]), "r"(af[3]),
                      "r"(bf[ni][0]), "r"(bf[ni][1]));
            }
        }
    }

    float* ob = O + (size_t)b * TT * DD + h * DHH;
    int r0 = i0 + wrow + g;
    int r1 = r0 + 8;
    float inv0 = (lst0 > 0.f) ? 1.0f / lst0 : 0.f;
    float inv1 = (lst1 > 0.f) ? 1.0f / lst1 : 0.f;
#pragma unroll
    for (int ni = 0; ni < 8; ni++) {
        int cb = ni * 8 + 2 * t;
        *(float2*)(ob + (size_t)r0 * DD + cb) =
            make_float2(oacc[ni][0] * inv0, oacc[ni][1] * inv0);
        *(float2*)(ob + (size_t)r1 * DD + cb) =
            make_float2(oacc[ni][2] * inv1, oacc[ni][3] * inv1);
    }
}

// ---------------------------------------------------------------------------
extern "C" void kernel_launch(void* const* d_in, const int* in_sizes, int n_in,
                              void* d_out, int out_size) {
    const float* x_in    = (const float*)d_in[0];
    const float* m       = (const float*)d_in[1];
    const int*   l       = (const int*)d_in[2];
    const float* Wqkv    = (const float*)d_in[3];
    const float* Wout    = (const float*)d_in[4];
    const float* bout    = (const float*)d_in[5];
    const float* ad_attn = (const float*)d_in[6];
    const float* ad_ffn  = (const float*)d_in[7];
    const float* W1      = (const float*)d_in[8];
    const float* b1      = (const float*)d_in[9];
    const float* W2      = (const float*)d_in[10];
    const float* b2      = (const float*)d_in[11];
    float* x = (float*)d_out;

    float *h, *qkv, *attn, *f1;
    cudaGetSymbolAddress((void**)&h,    g_h);
    cudaGetSymbolAddress((void**)&qkv,  g_qkv);
    cudaGetSymbolAddress((void**)&attn, g_attn);
    cudaGetSymbolAddress((void**)&f1,   g_f1);

    cudaFuncSetAttribute(flash_kernel,
                         cudaFuncAttributeMaxDynamicSharedMemorySize, FA_SMEM);

    cudaMemcpyAsync(x, x_in, sizeof(float) * (size_t)NROWS * DD,
                    cudaMemcpyDeviceToDevice);

    for (int i = 0; i < NLAY; i++) {
        // attention sub-block
        adaln_kernel<<<NROWS, 256>>>(x, m, l, ad_attn + (size_t)i * NLEV * 2 * DD, h);
        gemm_tf32<0><<<dim3(3 * DD / 128, NROWS / 128), 256>>>(
            h, Wqkv + (size_t)i * DD * 3 * DD, nullptr, nullptr, nullptr,
            qkv, NROWS, 3 * DD, DD);
        flash_kernel<<<dim3(TT / 128, BB * HH), 256, FA_SMEM>>>(qkv, m, attn);
        gemm_tf32<2><<<dim3(DD / 128, NROWS / 128), 256>>>(
            attn, Wout + (size_t)i * DD * DD, bout + (size_t)i * DD, x, m,
            x, NROWS, DD, DD);
        // FFN sub-block
        adaln_kernel<<<NROWS, 256>>>(x, m, l, ad_ffn + (size_t)i * NLEV * 2 * DD, h);
        gemm_tf32<1><<<dim3(DFF / 128, NROWS / 128), 256>>>(
            h, W1 + (size_t)i * DD * DFF, b1 + (size_t)i * DFF, nullptr, nullptr,
            f1, NROWS, DFF, DD);
        gemm_tf32<2><<<dim3(DD / 128, NROWS / 128), 256>>>(
            f1, W2 + (size_t)i * DFF * DD, b2 + (size_t)i * DD, x, m,
            x, NROWS, DD, DFF);
    }
}

// round 8
// speedup vs baseline: 4.1585x; 1.0251x over previous
#include <cuda_runtime.h>
#include <math.h>
#include <stdint.h>

// Problem constants
#define BB    2
#define TT    1024
#define DD    1024
#define HH    16
#define DHH   64
#define NLAY  4
#define NLEV  8
#define DFF   4096
#define NROWS (BB*TT)
#define FMAXV 3.402823466e38f

// Scratch (device globals — no allocation allowed)
__device__ float g_h[NROWS * DD];
__device__ float g_qkv[NROWS * 3 * DD];
__device__ float g_attn[NROWS * DD];
__device__ float g_f1[NROWS * DFF];

__device__ __forceinline__ float gelu_exact(float x) {
    return 0.5f * x * (1.0f + erff(x * 0.70710678118654752f));
}

__device__ __forceinline__ float cvt_tf32(float x) {
    uint32_t u;
    asm("cvt.rna.tf32.f32 %0, %1;" : "=r"(u) : "f"(x));
    return __uint_as_float(u);
}

__device__ __forceinline__ uint32_t cvt_tf32_u(float x) {
    uint32_t u;
    asm("cvt.rna.tf32.f32 %0, %1;" : "=r"(u) : "f"(x));
    return u;
}

__device__ __forceinline__ void cp_async16(void* smem, const void* gmem) {
    uint32_t s = (uint32_t)__cvta_generic_to_shared(smem);
    asm volatile("cp.async.cg.shared.global [%0], [%1], 16;" :: "r"(s), "l"(gmem));
}

// ---------------------------------------------------------------------------
// AdaLN  (output tf32-pre-rounded: it only feeds GEMM A operands)
// ---------------------------------------------------------------------------
__global__ void adaln_kernel(const float* __restrict__ x, const float* __restrict__ m,
                             const int* __restrict__ l, const float* __restrict__ emb,
                             float* __restrict__ out) {
    int row = blockIdx.x;
    int b = row / TT;
    float mv = m[row];
    const float* xr = x + (size_t)row * DD;
    float* orow = out + (size_t)row * DD;
    int tid = threadIdx.x;

    float v[4];
    float s = 0.f, ss = 0.f;
#pragma unroll
    for (int u = 0; u < 4; u++) {
        v[u] = xr[tid + u * 256];
        s += v[u];
        ss += v[u] * v[u];
    }
    __shared__ float sh1[256];
    __shared__ float sh2[256];
    sh1[tid] = s; sh2[tid] = ss;
    __syncthreads();
    for (int stp = 128; stp > 0; stp >>= 1) {
        if (tid < stp) { sh1[tid] += sh1[tid + stp]; sh2[tid] += sh2[tid + stp]; }
        __syncthreads();
    }
    float mu  = sh1[0] * (1.0f / DD);
    float var = sh2[0] * (1.0f / DD) - mu * mu;
    float rinv = rsqrtf(var + 1e-5f);

    const float* g = emb + (size_t)l[b] * (2 * DD);
#pragma unroll
    for (int u = 0; u < 4; u++) {
        int d = tid + u * 256;
        float hn = (v[u] - mu) * rinv;
        float h = 2.0f * (1.0f - 0.1f * hn) * hn;
        orow[d] = cvt_tf32((expf(g[d]) * h + g[DD + d]) * mv);
    }
}

// ---------------------------------------------------------------------------
// tf32 tensor-core GEMM, 2-stage cp.async pipeline: C = epi(A @ W + bias)
// A is assumed pre-rounded to tf32 (raw-bit fragments); W converted on load.
// BM: 128 or 64 (row-tile). N-tile fixed at 128, BK=32, 256 threads.
// EPI: 0 = none (store tf32-rounded), 1 = GELU (store tf32-rounded),
//      2 = residual+mask  C = (res + gemm + bias)*m[row]  (full fp32 store)
// ---------------------------------------------------------------------------
template <int BM, int EPI>
__global__ void __launch_bounds__(256, 2)
gemm_tf32(const float* __restrict__ A, const float* __restrict__ W,
          const float* __restrict__ bias, const float* __restrict__ res,
          const float* __restrict__ m, float* __restrict__ C,
          int M, int N, int K) {
    constexpr int MI = BM / 32;                    // 16-row frags per warp
    __shared__ __align__(16) float As[2][BM][36];
    __shared__ __align__(16) float Bs[2][32][136];

    int tid  = threadIdx.x;
    int warp = tid >> 5, lane = tid & 31;
    int g = lane >> 2, t = lane & 3;
    int warpm = warp >> 2, warpn = warp & 3;
    int row0 = blockIdx.y * BM, col0 = blockIdx.x * 128;

    float acc[MI][4][4] = {};

    int ar = tid >> 3, ac4 = (tid & 7) * 4;       // A: rows ar + i*32
    int br = tid >> 5, bc4 = (tid & 31) * 4;      // B: rows br + i*8

#define ISSUE_TILE(buf, k0)                                                     \
    {                                                                           \
        _Pragma("unroll")                                                       \
        for (int i = 0; i < BM / 32; i++)                                       \
            cp_async16(&As[buf][ar + i * 32][ac4],                              \
                       A + (size_t)(row0 + ar + i * 32) * K + (k0) + ac4);      \
        _Pragma("unroll")                                                       \
        for (int i = 0; i < 4; i++)                                             \
            cp_async16(&Bs[buf][br + i * 8][bc4],                               \
                       W + (size_t)((k0) + br + i * 8) * N + col0 + bc4);       \
        asm volatile("cp.async.commit_group;");                                 \
    }

    ISSUE_TILE(0, 0)
    ISSUE_TILE(1, 32)

    int buf = 0;
    for (int k0 = 0; k0 < K; k0 += 32) {
        if (k0 + 32 < K) {
            asm volatile("cp.async.wait_group 1;");
        } else {
            asm volatile("cp.async.wait_group 0;");
        }
        __syncthreads();

#pragma unroll
        for (int kk = 0; kk < 32; kk += 8) {
            uint32_t af[MI][4], bf[4][2];
#pragma unroll
            for (int mi = 0; mi < MI; mi++) {
                int rb = warpm * (BM / 2) + mi * 16 + g;
                af[mi][0] = __float_as_uint(As[buf][rb    ][kk + t    ]);
                af[mi][1] = __float_as_uint(As[buf][rb + 8][kk + t    ]);
                af[mi][2] = __float_as_uint(As[buf][rb    ][kk + t + 4]);
                af[mi][3] = __float_as_uint(As[buf][rb + 8][kk + t + 4]);
            }
#pragma unroll
            for (int ni = 0; ni < 4; ni++) {
                int cb = warpn * 32 + ni * 8 + g;
                bf[ni][0] = cvt_tf32_u(Bs[buf][kk + t    ][cb]);
                bf[ni][1] = cvt_tf32_u(Bs[buf][kk + t + 4][cb]);
            }
#pragma unroll
            for (int mi = 0; mi < MI; mi++)
#pragma unroll
                for (int ni = 0; ni < 4; ni++) {
                    asm volatile(
                        "mma.sync.aligned.m16n8k8.row.col.f32.tf32.tf32.f32 "
                        "{%0,%1,%2,%3}, {%4,%5,%6,%7}, {%8,%9}, {%0,%1,%2,%3};"
                        : "+f"(acc[mi][ni][0]), "+f"(acc[mi][ni][1]),
                          "+f"(acc[mi][ni][2]), "+f"(acc[mi][ni][3])
                        : "r"(af[mi][0]), "r"(af[mi][1]), "r"(af[mi][2]), "r"(af[mi][3]),
                          "r"(bf[ni][0]), "r"(bf[ni][1]));
                }
        }
        __syncthreads();
        if (k0 + 64 < K) {
            ISSUE_TILE(buf, k0 + 64)
        }
        buf ^= 1;
    }
#undef ISSUE_TILE

#pragma unroll
    for (int mi = 0; mi < MI; mi++) {
        int r0 = row0 + warpm * (BM / 2) + mi * 16 + g;
        int r1 = r0 + 8;
        float m0 = (EPI == 2) ? m[r0] : 0.f;
        float m1 = (EPI == 2) ? m[r1] : 0.f;
#pragma unroll
        for (int ni = 0; ni < 4; ni++) {
            int cb = col0 + warpn * 32 + ni * 8 + 2 * t;
            float v0 = acc[mi][ni][0], v1 = acc[mi][ni][1];
            float v2 = acc[mi][ni][2], v3 = acc[mi][ni][3];
            if (bias) {
                float b0 = bias[cb], b1 = bias[cb + 1];
                v0 += b0; v1 += b1; v2 += b0; v3 += b1;
            }
            if (EPI == 1) {
                v0 = gelu_exact(v0); v1 = gelu_exact(v1);
                v2 = gelu_exact(v2); v3 = gelu_exact(v3);
            }
            if (EPI == 2) {
                const float* rr0 = res + (size_t)r0 * N + cb;
                const float* rr1 = res + (size_t)r1 * N + cb;
                v0 = (rr0[0] + v0) * m0; v1 = (rr0[1] + v1) * m0;
                v2 = (rr1[0] + v2) * m1; v3 = (rr1[1] + v3) * m1;
            } else {
                // outputs feed tf32 GEMM/attention A operands: pre-round at store
                v0 = cvt_tf32(v0); v1 = cvt_tf32(v1);
                v2 = cvt_tf32(v2); v3 = cvt_tf32(v3);
            }
            *(float2*)(C + (size_t)r0 * N + cb) = make_float2(v0, v1);
            *(float2*)(C + (size_t)r1 * N + cb) = make_float2(v2, v3);
        }
    }
}

// ---------------------------------------------------------------------------
// Flash attention (tf32 MMA): 8 warps; warp w owns rows [w*16, w*16+16)
// across all 64 j-columns. qkv is pre-rounded tf32, so loads are raw copies.
// smem: Q[128][68] | K[64][68] | V[64][68] | P[128][68]
// ---------------------------------------------------------------------------
#define FA_SMEM ((128*68 + 64*68 + 64*68 + 128*68) * 4)

__global__ void __launch_bounds__(256)
flash_kernel(const float* __restrict__ qkv, const float* __restrict__ mk,
             float* __restrict__ O) {
    extern __shared__ float sm[];
    float (*Qs)[68] = (float(*)[68])sm;
    float (*Ks)[68] = (float(*)[68])(sm + 128 * 68);
    float (*Vs)[68] = (float(*)[68])(sm + 128 * 68 + 64 * 68);
    float (*Ps)[68] = (float(*)[68])(sm + 128 * 68 + 2 * 64 * 68);

    int z = blockIdx.y; int b = z >> 4; int h = z & 15;
    int it = gridDim.x - 1 - blockIdx.x;        // heavy tiles first
    int i0 = it * 128;
    int tid = threadIdx.x;
    int warp = tid >> 5, lane = tid & 31;
    int g = lane >> 2, t = lane & 3;
    int wrow = warp * 16;

    const float* qb = qkv + (size_t)b * TT * 3 * DD + h * DHH;
    const float* kb = qb + DD;
    const float* vb = qb + 2 * DD;
    const float* mrow = mk + b * TT;

#pragma unroll
    for (int i = 0; i < 8; i++) {
        int idx = tid + i * 256;
        int r = idx >> 4, c4 = (idx & 15) * 4;
        *(float4*)&Qs[r][c4] = *(const float4*)(qb + (size_t)(i0 + r) * (3 * DD) + c4);
    }

    float oacc[8][4] = {};
    float mst0 = -FMAXV, mst1 = -FMAXV;
    float lst0 = 0.f,    lst1 = 0.f;

    int jend = i0 + 128;
    for (int j0 = 0; j0 < jend; j0 += 64) {
        __syncthreads();
#pragma unroll
        for (int i = 0; i < 4; i++) {
            int idx = tid + i * 256;
            int r = idx >> 4, c4 = (idx & 15) * 4;
            *(float4*)&Ks[r][c4] = *(const float4*)(kb + (size_t)(j0 + r) * (3 * DD) + c4);
            *(float4*)&Vs[r][c4] = *(const float4*)(vb + (size_t)(j0 + r) * (3 * DD) + c4);
        }
        __syncthreads();

        // S = Q @ K^T : warp computes 16 x 64
        float sacc[8][4] = {};
#pragma unroll
        for (int kk = 0; kk < 64; kk += 8) {
            uint32_t af[4], bf[8][2];
            af[0] = __float_as_uint(Qs[wrow + g    ][kk + t    ]);
            af[1] = __float_as_uint(Qs[wrow + g + 8][kk + t    ]);
            af[2] = __float_as_uint(Qs[wrow + g    ][kk + t + 4]);
            af[3] = __float_as_uint(Qs[wrow + g + 8][kk + t + 4]);
#pragma unroll
            for (int ni = 0; ni < 8; ni++) {
                int cb = ni * 8 + g;
                bf[ni][0] = __float_as_uint(Ks[cb][kk + t    ]);
                bf[ni][1] = __float_as_uint(Ks[cb][kk + t + 4]);
            }
#pragma unroll
            for (int ni = 0; ni < 8; ni++) {
                asm volatile(
                    "mma.sync.aligned.m16n8k8.row.col.f32.tf32.tf32.f32 "
                    "{%0,%1,%2,%3}, {%4,%5,%6,%7}, {%8,%9}, {%0,%1,%2,%3};"
                    : "+f"(sacc[ni][0]), "+f"(sacc[ni][1]),
                      "+f"(sacc[ni][2]), "+f"(sacc[ni][3])
                    : "r"(af[0]), "r"(af[1]), "r"(af[2]), "r"(af[3]),
                      "r"(bf[ni][0]), "r"(bf[ni][1]));
            }
        }

        int row0 = i0 + wrow + g;
        int row1 = row0 + 8;
#pragma unroll
        for (int ni = 0; ni < 8; ni++) {
            int j = j0 + ni * 8 + 2 * t;
            float km0 = mrow[j], km1 = mrow[j + 1];
            bool ok00 = (j     <= row0) && (km0 != 0.f);
            bool ok01 = (j + 1 <= row0) && (km1 != 0.f);
            bool ok10 = (j     <= row1) && (km0 != 0.f);
            bool ok11 = (j + 1 <= row1) && (km1 != 0.f);
            sacc[ni][0] = ok00 ? sacc[ni][0] * 0.125f : -FMAXV;
            sacc[ni][1] = ok01 ? sacc[ni][1] * 0.125f : -FMAXV;
            sacc[ni][2] = ok10 ? sacc[ni][2] * 0.125f : -FMAXV;
            sacc[ni][3] = ok11 ? sacc[ni][3] * 0.125f : -FMAXV;
        }

        float mx0 = -FMAXV, mx1 = -FMAXV;
#pragma unroll
        for (int ni = 0; ni < 8; ni++) {
            mx0 = fmaxf(mx0, fmaxf(sacc[ni][0], sacc[ni][1]));
            mx1 = fmaxf(mx1, fmaxf(sacc[ni][2], sacc[ni][3]));
        }
        mx0 = fmaxf(mx0, __shfl_xor_sync(0xffffffff, mx0, 1));
        mx0 = fmaxf(mx0, __shfl_xor_sync(0xffffffff, mx0, 2));
        mx1 = fmaxf(mx1, __shfl_xor_sync(0xffffffff, mx1, 1));
        mx1 = fmaxf(mx1, __shfl_xor_sync(0xffffffff, mx1, 2));

        float nm0 = fmaxf(mst0, mx0);
        float nm1 = fmaxf(mst1, mx1);
        float a0 = expf(mst0 - nm0);
        float a1 = expf(mst1 - nm1);
        mst0 = nm0; mst1 = nm1;

        float rs0 = 0.f, rs1 = 0.f;
#pragma unroll
        for (int ni = 0; ni < 8; ni++) {
            float p0 = expf(sacc[ni][0] - nm0);
            float p1 = expf(sacc[ni][1] - nm0);
            float p2 = expf(sacc[ni][2] - nm1);
            float p3 = expf(sacc[ni][3] - nm1);
            sacc[ni][0] = p0; sacc[ni][1] = p1;
            sacc[ni][2] = p2; sacc[ni][3] = p3;
            rs0 += p0 + p1; rs1 += p2 + p3;
        }
        rs0 += __shfl_xor_sync(0xffffffff, rs0, 1);
        rs0 += __shfl_xor_sync(0xffffffff, rs0, 2);
        rs1 += __shfl_xor_sync(0xffffffff, rs1, 1);
        rs1 += __shfl_xor_sync(0xffffffff, rs1, 2);
        lst0 = lst0 * a0 + rs0;
        lst1 = lst1 * a1 + rs1;

#pragma unroll
        for (int ni = 0; ni < 8; ni++) {
            oacc[ni][0] *= a0; oacc[ni][1] *= a0;
            oacc[ni][2] *= a1; oacc[ni][3] *= a1;
        }

#pragma unroll
        for (int ni = 0; ni < 8; ni++) {
            int lc = ni * 8 + 2 * t;
            Ps[wrow + g    ][lc]     = cvt_tf32(sacc[ni][0]);
            Ps[wrow + g    ][lc + 1] = cvt_tf32(sacc[ni][1]);
            Ps[wrow + g + 8][lc]     = cvt_tf32(sacc[ni][2]);
            Ps[wrow + g + 8][lc + 1] = cvt_tf32(sacc[ni][3]);
        }
        __syncwarp();

        // O += P @ V
#pragma unroll
        for (int kk = 0; kk < 64; kk += 8) {
            uint32_t af[4], bf[8][2];
            af[0] = __float_as_uint(Ps[wrow + g    ][kk + t    ]);
            af[1] = __float_as_uint(Ps[wrow + g + 8][kk + t    ]);
            af[2] = __float_as_uint(Ps[wrow + g    ][kk + t + 4]);
            af[3] = __float_as_uint(Ps[wrow + g + 8][kk + t + 4]);
#pragma unroll
            for (int ni = 0; ni < 8; ni++) {
                int cb = ni * 8 + g;
                bf[ni][0] = __float_as_uint(Vs[kk + t    ][cb]);
                bf[ni][1] = __float_as_uint(Vs[kk + t + 4][cb]);
            }
#pragma unroll
            for (int ni = 0; ni < 8; ni++) {
                asm volatile(
                    "mma.sync.aligned.m16n8k8.row.col.f32.tf32.tf32.f32 "
                    "{%0,%1,%2,%3}, {%4,%5,%6,%7}, {%8,%9}, {%0,%1,%2,%3};"
                    : "+f"(oacc[ni][0]), "+f"(oacc[ni][1]),
                      "+f"(oacc[ni][2]), "+f"(oacc[ni][3])
                    : "r"(af[0]), "r"(af[1]), "r"(af[2]), "r"(af[3]),
                      "r"(bf[ni][0]), "r"(bf[ni][1]));
            }
        }
    }

    // epilogue: O / l -> g_attn (pre-rounded tf32: feeds Wout GEMM A)
    float* ob = O + (size_t)b * TT * DD + h * DHH;
    int r0 = i0 + wrow + g;
    int r1 = r0 + 8;
    float inv0 = (lst0 > 0.f) ? 1.0f / lst0 : 0.f;
    float inv1 = (lst1 > 0.f) ? 1.0f / lst1 : 0.f;
#pragma unroll
    for (int ni = 0; ni < 8; ni++) {
        int cb = ni * 8 + 2 * t;
        *(float2*)(ob + (size_t)r0 * DD + cb) =
            make_float2(cvt_tf32(oacc[ni][0] * inv0), cvt_tf32(oacc[ni][1] * inv0));
        *(float2*)(ob + (size_t)r1 * DD + cb) =
            make_float2(cvt_tf32(oacc[ni][2] * inv1), cvt_tf32(oacc[ni][3] * inv1));
    }
}

// ---------------------------------------------------------------------------
extern "C" void kernel_launch(void* const* d_in, const int* in_sizes, int n_in,
                              void* d_out, int out_size) {
    const float* x_in    = (const float*)d_in[0];
    const float* m       = (const float*)d_in[1];
    const int*   l       = (const int*)d_in[2];
    const float* Wqkv    = (const float*)d_in[3];
    const float* Wout    = (const float*)d_in[4];
    const float* bout    = (const float*)d_in[5];
    const float* ad_attn = (const float*)d_in[6];
    const float* ad_ffn  = (const float*)d_in[7];
    const float* W1      = (const float*)d_in[8];
    const float* b1      = (const float*)d_in[9];
    const float* W2      = (const float*)d_in[10];
    const float* b2      = (const float*)d_in[11];
    float* x = (float*)d_out;

    float *h, *qkv, *attn, *f1;
    cudaGetSymbolAddress((void**)&h,    g_h);
    cudaGetSymbolAddress((void**)&qkv,  g_qkv);
    cudaGetSymbolAddress((void**)&attn, g_attn);
    cudaGetSymbolAddress((void**)&f1,   g_f1);

    cudaFuncSetAttribute(flash_kernel,
                         cudaFuncAttributeMaxDynamicSharedMemorySize, FA_SMEM);

    cudaMemcpyAsync(x, x_in, sizeof(float) * (size_t)NROWS * DD,
                    cudaMemcpyDeviceToDevice);

    for (int i = 0; i < NLAY; i++) {
        // attention sub-block
        adaln_kernel<<<NROWS, 256>>>(x, m, l, ad_attn + (size_t)i * NLEV * 2 * DD, h);
        gemm_tf32<128, 0><<<dim3(3 * DD / 128, NROWS / 128), 256>>>(
            h, Wqkv + (size_t)i * DD * 3 * DD, nullptr, nullptr, nullptr,
            qkv, NROWS, 3 * DD, DD);
        flash_kernel<<<dim3(TT / 128, BB * HH), 256, FA_SMEM>>>(qkv, m, attn);
        gemm_tf32<64, 2><<<dim3(DD / 128, NROWS / 64), 256>>>(
            attn, Wout + (size_t)i * DD * DD, bout + (size_t)i * DD, x, m,
            x, NROWS, DD, DD);
        // FFN sub-block
        adaln_kernel<<<NROWS, 256>>>(x, m, l, ad_ffn + (size_t)i * NLEV * 2 * DD, h);
        gemm_tf32<128, 1><<<dim3(DFF / 128, NROWS / 128), 256>>>(
            h, W1 + (size_t)i * DD * DFF, b1 + (size_t)i * DFF, nullptr, nullptr,
            f1, NROWS, DFF, DD);
        gemm_tf32<64, 2><<<dim3(DD / 128, NROWS / 64), 256>>>(
            f1, W2 + (size_t)i * DFF * DD, b2 + (size_t)i * DD, x, m,
            x, NROWS, DD, DFF);
    }
}